// round 9
// baseline (speedup 1.0000x reference)
#include <cuda_runtime.h>
#include <cuda_bf16.h>
#include <math.h>
#include <stdint.h>

// Problem constants
#define NB     4
#define NPTS   2048
#define NTOT   4096
#define D      64
#define BM     128           // tile side (points)
#define TILES  32
#define NTRI   528           // TILES*(TILES+1)/2
#define NTASK  (NTRI * NB)   // 2112
#define SW     36            // smem row stride in 32-bit words (144B)
#define SLABS  32            // stats slabs (128 points each)
#define LOG2E  1.44269504088896340736f

// Scratch (device globals — no allocation allowed)
__device__ float g_vec[NB][SLABS][D];
__device__ float g_s1[NB][SLABS];
__device__ float g_negc[NB];                  // -1/(4*bwb)
__device__ float g_sqn[NB][NTOT];             // per-point ||bf16(p)||^2
__device__ __nv_bfloat16 g_bf[NB][NTOT][D];   // bf16-rounded inputs (2MB)
__device__ float g_part[NB][NTRI];
__device__ int   g_arrive, g_release, g_fin;  // barrier state (reset in-kernel)
__device__ int   g_cnt2[NB];

typedef unsigned long long u64;

__device__ __forceinline__ float ex2f(float x) {
    float r;
    asm("ex2.approx.ftz.f32 %0, %1;" : "=f"(r) : "f"(x));
    return r;
}
__device__ __forceinline__ uint32_t pack_bf16x2(float lo, float hi) {
    __nv_bfloat162 p = __floats2bfloat162_rn(lo, hi);
    return *(uint32_t*)&p;
}
__device__ __forceinline__ uint32_t smem_u32(const void* p) {
    uint32_t a;
    asm("{ .reg .u64 t; cvta.to.shared.u64 t, %1; cvt.u32.u64 %0, t; }" : "=r"(a) : "l"(p));
    return a;
}
__device__ __forceinline__ void ldsm_x4(uint32_t* r, uint32_t addr) {
    asm volatile("ldmatrix.sync.aligned.m8n8.x4.shared.b16 {%0,%1,%2,%3}, [%4];"
        : "=r"(r[0]), "=r"(r[1]), "=r"(r[2]), "=r"(r[3]) : "r"(addr));
}
__device__ __forceinline__ void mma_bf16(float* c, const uint32_t* a, const uint32_t* bf) {
    asm volatile(
        "mma.sync.aligned.m16n8k16.row.col.f32.bf16.bf16.f32 "
        "{%0,%1,%2,%3}, {%4,%5,%6,%7}, {%8,%9}, {%0,%1,%2,%3};"
        : "+f"(c[0]), "+f"(c[1]), "+f"(c[2]), "+f"(c[3])
        : "r"(a[0]), "r"(a[1]), "r"(a[2]), "r"(a[3]), "r"(bf[0]), "r"(bf[1]));
}
// packed f32x2 (Blackwell)
__device__ __forceinline__ u64 pk2(float lo, float hi) {
    u64 r; asm("mov.b64 %0, {%1, %2};" : "=l"(r) : "f"(lo), "f"(hi)); return r;
}
__device__ __forceinline__ void upk2(float& lo, float& hi, u64 v) {
    asm("mov.b64 {%0, %1}, %2;" : "=f"(lo), "=f"(hi) : "l"(v));
}
__device__ __forceinline__ u64 fma2(u64 a, u64 b, u64 c) {
    u64 d; asm("fma.rn.f32x2 %0, %1, %2, %3;" : "=l"(d) : "l"(a), "l"(b), "l"(c)); return d;
}
__device__ __forceinline__ u64 mul2(u64 a, u64 b) {
    u64 d; asm("mul.rn.f32x2 %0, %1, %2;" : "=l"(d) : "l"(a), "l"(b)); return d;
}
__device__ __forceinline__ u64 add2(u64 a, u64 b) {
    u64 d; asm("add.rn.f32x2 %0, %1, %2;" : "=l"(d) : "l"(a), "l"(b)); return d;
}
__device__ __forceinline__ void cp16(uint32_t smem, const void* gmem) {
    asm volatile("cp.async.cg.shared.global [%0], [%1], 16;"
                 :: "r"(smem), "l"(gmem) : "memory");
}
__device__ __forceinline__ void decode_tri(int tri, int& by, int& bx) {
    int y = (int)((sqrtf(8.f * (float)tri + 1.f) - 1.f) * 0.5f);
    while ((y + 1) * (y + 2) / 2 <= tri) ++y;
    while (y * (y + 1) / 2 > tri) --y;
    by = y;
    bx = tri - y * (y + 1) / 2;
}

// ---------------------------------------------------------------------------
// Single persistent kernel: stats -> grid barrier (finalize) -> tile loop.
// grid = 3 * numSMs (full residency guaranteed by __launch_bounds__(256,3)).
// ---------------------------------------------------------------------------
__global__ void __launch_bounds__(256, 3)
mmd_persist_kernel(const float* __restrict__ x, const float* __restrict__ y,
                   float* __restrict__ out) {
    extern __shared__ float sm[];
    uint32_t* As = (uint32_t*)sm;                     // [128][SW] bf16x2 words
    uint32_t* Bs = As + BM * SW;
    float* sqA = (float*)(Bs + BM * SW);              // [128] pre-scaled by negc2
    float* sqB = sqA + BM;

    const int t = threadIdx.x;
    const int w = t >> 5, lane = t & 31;
    const int gid = lane >> 2, tig = lane & 3;
    const int bid = blockIdx.x;
    const int nblk = gridDim.x;

    // =======================================================================
    // Phase A: stats + bf16 conversion (blocks 0..127; one 128-pt slab each)
    // =======================================================================
    if (bid < SLABS * NB) {
        const int b = bid & 3, s = bid >> 2;
        const int d = t & 63, g = t >> 6;
        const int pbase = s * 128 + g * 32;
        const float* base = (pbase < NPTS)
            ? x + ((size_t)b * NPTS + pbase) * D
            : y + ((size_t)b * NPTS + (pbase - NPTS)) * D;

        float vsum = 0.f, ssum = 0.f;
        #pragma unroll 8
        for (int r = 0; r < 32; ++r) {
            float v = base[(size_t)r * D + d];
            vsum += v;
            ssum = fmaf(v, v, ssum);
        }
        __shared__ float sv[4][64];
        __shared__ float ssr[256];
        sv[g][d] = vsum;
        ssr[t] = ssum;
        __syncthreads();
        if (t < 64) g_vec[b][s][t] = sv[0][t] + sv[1][t] + sv[2][t] + sv[3][t];
        for (int o = 128; o > 0; o >>= 1) {
            if (t < o) ssr[t] += ssr[t + o];
            __syncthreads();
        }
        if (t == 0) g_s1[b][s] = ssr[0];

        // bf16 conversion + squared norm: 2 threads per point
        {
            const int p0 = s * 128 + (t >> 1);
            const int half = t & 1;
            const float* row = ((p0 < NPTS)
                ? x + ((size_t)b * NPTS + p0) * D
                : y + ((size_t)b * NPTS + (p0 - NPTS)) * D) + half * 32;
            uint2* dst = (uint2*)&g_bf[b][p0][half * 32];
            float acc = 0.f;
            #pragma unroll
            for (int k = 0; k < 8; ++k) {
                float4 v = *(const float4*)(row + k * 4);
                float a0 = __bfloat162float(__float2bfloat16(v.x));
                float a1 = __bfloat162float(__float2bfloat16(v.y));
                float a2 = __bfloat162float(__float2bfloat16(v.z));
                float a3 = __bfloat162float(__float2bfloat16(v.w));
                acc = fmaf(a0, a0, acc);
                acc = fmaf(a1, a1, acc);
                acc = fmaf(a2, a2, acc);
                acc = fmaf(a3, a3, acc);
                uint2 pk;
                pk.x = pack_bf16x2(v.x, v.y);
                pk.y = pack_bf16x2(v.z, v.w);
                dst[k] = pk;
            }
            float other = __shfl_xor_sync(0xffffffffu, acc, 1);
            if (half == 0) g_sqn[b][p0] = acc + other;
        }
    }

    // =======================================================================
    // Grid barrier: last-arriving block finalizes bandwidth, releases all.
    // =======================================================================
    __threadfence();
    __syncthreads();
    __shared__ int lastblk;
    if (t == 0) {
        int old = atomicAdd(&g_arrive, 1);
        lastblk = (old == nblk - 1);
    }
    __syncthreads();

    if (lastblk) {
        __threadfence();
        const int bb = t >> 6, d = t & 63;
        float v = 0.f;
        #pragma unroll
        for (int s2 = 0; s2 < SLABS; ++s2) v += g_vec[bb][s2][d];
        float vv = v * v;
        #pragma unroll
        for (int o = 16; o > 0; o >>= 1) vv += __shfl_down_sync(0xffffffffu, vv, o);
        __shared__ float redf[8];
        if ((t & 31) == 0) redf[t >> 5] = vv;
        __syncthreads();
        if (t < NB) {
            float VV = redf[2 * t] + redf[2 * t + 1];
            float S1 = 0.f;
            #pragma unroll
            for (int s2 = 0; s2 < SLABS; ++s2) S1 += g_s1[t][s2];
            float sumL2 = 2.f * (float)NTOT * S1 - 2.f * VV;
            float bwb = sumL2 / 16773120.f;   // N^2 - N
            g_negc[t] = -1.f / (4.f * bwb);
        }
        __syncthreads();
        __threadfence();
        if (t == 0) atomicExch(&g_release, 1);
    } else {
        if (t == 0) {
            while (atomicAdd(&g_release, 0) == 0) __nanosleep(64);
        }
        __syncthreads();
    }
    __threadfence();

    // =======================================================================
    // Phase B: persistent loop over tri-tile tasks with cp.async prefetch.
    // =======================================================================
    const uint32_t smb = smem_u32(sm);
    const uint32_t As_b = smb;
    const uint32_t Bs_b = smb + BM * SW * 4;

    // Loop-invariant ldmatrix addresses
    const int m0 = (w & 1) * 64;
    const int n0 = (w >> 1) * 32;
    uint32_t a_addr[4];
    #pragma unroll
    for (int mf = 0; mf < 4; ++mf) {
        int row = m0 + mf * 16 + (lane & 15);
        a_addr[mf] = As_b + (uint32_t)(row * SW + (lane >> 4) * 4) * 4u;
    }
    uint32_t b_addr_h[2];
    #pragma unroll
    for (int half = 0; half < 2; ++half) {
        const int bcol = n0 + half * 16 + ((lane >> 4) << 3) + (lane & 7);
        b_addr_h[half] = Bs_b + (uint32_t)(bcol * SW + ((lane >> 3) & 1) * 4) * 4u;
    }

    // Prefetch first task
    if (bid < NTASK) {
        int b0 = bid & 3, by0, bx0;
        decode_tri(bid >> 2, by0, bx0);
        const char* srcA = (const char*)&g_bf[b0][by0 * BM][0];
        const char* srcB = (const char*)&g_bf[b0][bx0 * BM][0];
        #pragma unroll
        for (int i = 0; i < 4; ++i) {
            int idx = t + i * 256;
            uint32_t off = (uint32_t)((idx >> 3) * (SW * 4) + (idx & 7) * 16);
            cp16(As_b + off, srcA + idx * 16);
            cp16(Bs_b + off, srcB + idx * 16);
        }
        asm volatile("cp.async.commit_group;" ::: "memory");
    }

    for (int task = bid; task < NTASK; task += nblk) {
        const int b = task & 3;
        int by, bx;
        decode_tri(task >> 2, by, bx);

        const float negc2 = g_negc[b] * LOG2E;
        const float m2v = -2.f * negc2;
        const u64 M2 = pk2(m2v, m2v);

        asm volatile("cp.async.wait_group 0;" ::: "memory");
        __syncthreads();                        // tile data ready; prev iter done

        // stage pre-scaled squared norms
        if (t < 128) sqA[t] = g_sqn[b][by * BM + t] * negc2;
        else         sqB[t - 128] = g_sqn[b][bx * BM + (t - 128)] * negc2;

        u64 acc2 = pk2(0.f, 0.f);
        #pragma unroll
        for (int half = 0; half < 2; ++half) {
            float c[4][2][4];
            #pragma unroll
            for (int mf = 0; mf < 4; ++mf)
                #pragma unroll
                for (int nf = 0; nf < 2; ++nf)
                    #pragma unroll
                    for (int q = 0; q < 4; ++q) c[mf][nf][q] = 0.f;

            #pragma unroll
            for (int ks = 0; ks < 4; ++ks) {
                uint32_t a[4][4], bf[4];
                #pragma unroll
                for (int mf = 0; mf < 4; ++mf) ldsm_x4(a[mf], a_addr[mf] + ks * 32);
                ldsm_x4(bf, b_addr_h[half] + ks * 32);
                #pragma unroll
                for (int mf = 0; mf < 4; ++mf) {
                    mma_bf16(c[mf][0], a[mf], &bf[0]);
                    mma_bf16(c[mf][1], a[mf], &bf[2]);
                }
            }

            __syncthreads();   // half0: sq visible. half1: all ldsm reads done.

            if (half == 1) {
                // prefetch next task's tiles (overwrites As/Bs during epilogue)
                int nxt = task + nblk;
                if (nxt < NTASK) {
                    int nb_ = nxt & 3, nby, nbx;
                    decode_tri(nxt >> 2, nby, nbx);
                    const char* srcA = (const char*)&g_bf[nb_][nby * BM][0];
                    const char* srcB = (const char*)&g_bf[nb_][nbx * BM][0];
                    #pragma unroll
                    for (int i = 0; i < 4; ++i) {
                        int idx = t + i * 256;
                        uint32_t off = (uint32_t)((idx >> 3) * (SW * 4) + (idx & 7) * 16);
                        cp16(As_b + off, srcA + idx * 16);
                        cp16(Bs_b + off, srcB + idx * 16);
                    }
                    asm volatile("cp.async.commit_group;" ::: "memory");
                }
            }

            // packed epilogue for this half
            const int nb2 = n0 + half * 16;
            #pragma unroll
            for (int mf = 0; mf < 4; ++mf) {
                const int r0i = m0 + mf * 16 + gid;
                const float sA0 = sqA[r0i], sA1 = sqA[r0i + 8];
                const u64 SA0 = pk2(sA0, sA0);
                const u64 SA1 = pk2(sA1, sA1);
                #pragma unroll
                for (int nf = 0; nf < 2; ++nf) {
                    const int c0i = nb2 + nf * 8 + tig * 2;
                    const u64 SB = pk2(sqB[c0i], sqB[c0i + 1]);
                    const u64 S0 = add2(SA0, SB);
                    const u64 S1 = add2(SA1, SB);
                    const float* cf = c[mf][nf];
                    #pragma unroll
                    for (int pr = 0; pr < 2; ++pr) {
                        u64 C = pk2(cf[pr * 2], cf[pr * 2 + 1]);
                        u64 L = fma2(M2, C, pr ? S1 : S0);
                        float l0, l1;
                        upk2(l0, l1, L);
                        u64 E = pk2(ex2f(l0), ex2f(l1));
                        u64 E2 = mul2(E, E);
                        u64 E4 = mul2(E2, E2);
                        u64 E8 = mul2(E4, E4);
                        u64 T = fma2(E8, E8, E8);     // e16 + e8
                        acc2 = add2(acc2, add2(add2(E, E2), add2(E4, T)));
                    }
                }
            }
        }

        float llo, lhi;
        upk2(llo, lhi, acc2);
        float local = llo + lhi;

        // block reduce + signed/weighted write + fused final reduce
        #pragma unroll
        for (int o = 16; o > 0; o >>= 1) local += __shfl_down_sync(0xffffffffu, local, o);
        __shared__ float red[8];
        if (lane == 0) red[w] = local;
        __syncthreads();

        __shared__ int islast;
        if (t == 0) {
            float tot = 0.f;
            #pragma unroll
            for (int ww = 0; ww < 8; ++ww) tot += red[ww];
            float sgn = ((by < 16) == (bx < 16)) ? 1.f : -1.f;
            float wt = (bx == by) ? 1.f : 2.f;
            g_part[b][task >> 2] = tot * sgn * wt;
            __threadfence();
            int old = atomicAdd(&g_cnt2[b], 1);
            islast = (old == NTRI - 1);
        }
        __syncthreads();

        if (islast) {
            float s = 0.f;
            for (int idx = t; idx < NTRI; idx += 256) s += g_part[b][idx];
            #pragma unroll
            for (int o = 16; o > 0; o >>= 1) s += __shfl_down_sync(0xffffffffu, s, o);
            __shared__ float red2[8];
            if (lane == 0) red2[w] = s;
            __syncthreads();
            if (t == 0) {
                float tot = 0.f;
                #pragma unroll
                for (int ww = 0; ww < 8; ++ww) tot += red2[ww];
                out[b] = tot * (1.f / ((float)NPTS * (float)NPTS));
                g_cnt2[b] = 0;   // reset for graph replay
            }
        }
    }

    // Reset barrier state for graph replay (last block to finish everything)
    __syncthreads();
    if (t == 0) {
        int old = atomicAdd(&g_fin, 1);
        if (old == nblk - 1) {
            g_arrive = 0;
            g_release = 0;
            g_fin = 0;
            __threadfence();
        }
    }
}

extern "C" void kernel_launch(void* const* d_in, const int* in_sizes, int n_in,
                              void* d_out, int out_size) {
    const float* x = (const float*)d_in[0];
    const float* y = (const float*)d_in[1];
    float* out = (float*)d_out;

    int dev = 0, sms = 148;
    cudaGetDevice(&dev);
    cudaDeviceGetAttribute(&sms, cudaDevAttrMultiProcessorCount, dev);
    int nblk = sms * 3;                 // residency guaranteed by launch_bounds(256,3)
    if (nblk > NTASK) nblk = NTASK;

    const int smem_bytes = (2 * BM * SW + 2 * BM) * (int)sizeof(float);  // 37888
    cudaFuncSetAttribute(mmd_persist_kernel,
                         cudaFuncAttributeMaxDynamicSharedMemorySize, smem_bytes);

    mmd_persist_kernel<<<nblk, 256, smem_bytes>>>(x, y, out);
}

// round 10
// speedup vs baseline: 1.0960x; 1.0960x over previous
#include <cuda_runtime.h>
#include <cuda_bf16.h>
#include <math.h>
#include <stdint.h>

// Problem constants
#define NB     4
#define NPTS   2048
#define NTOT   4096
#define D      64
#define BM     128           // tile side (points)
#define TILES  32
#define NTRI   528           // TILES*(TILES+1)/2
#define SW     36            // smem row stride in 32-bit words (144B)
#define SLABS  32            // stats slabs (128 points each)
#define LOG2E  1.44269504088896340736f

// Scratch (device globals — no allocation allowed)
__device__ float g_vec[NB][SLABS][D];
__device__ float g_s1[NB][SLABS];
__device__ float g_negc[NB];                  // -1/(4*bwb)
__device__ float g_sqn[NB][NTOT];             // per-point ||bf16(p)||^2
__device__ __nv_bfloat16 g_bf[NB][NTOT][D];   // bf16-rounded inputs (2MB)
__device__ float g_part[NB][NTRI];
__device__ int   g_cnt1;
__device__ int   g_cnt2[NB];

typedef unsigned long long u64;

__device__ __forceinline__ float ex2f(float x) {
    float r;
    asm("ex2.approx.ftz.f32 %0, %1;" : "=f"(r) : "f"(x));
    return r;
}
__device__ __forceinline__ uint32_t pack_bf16x2(float lo, float hi) {
    __nv_bfloat162 p = __floats2bfloat162_rn(lo, hi);
    return *(uint32_t*)&p;
}
__device__ __forceinline__ uint32_t smem_u32(const void* p) {
    uint32_t a;
    asm("{ .reg .u64 t; cvta.to.shared.u64 t, %1; cvt.u32.u64 %0, t; }" : "=r"(a) : "l"(p));
    return a;
}
__device__ __forceinline__ void ldsm_x4(uint32_t* r, uint32_t addr) {
    asm volatile("ldmatrix.sync.aligned.m8n8.x4.shared.b16 {%0,%1,%2,%3}, [%4];"
        : "=r"(r[0]), "=r"(r[1]), "=r"(r[2]), "=r"(r[3]) : "r"(addr));
}
__device__ __forceinline__ void mma_bf16(float* c, const uint32_t* a, const uint32_t* bf) {
    asm volatile(
        "mma.sync.aligned.m16n8k16.row.col.f32.bf16.bf16.f32 "
        "{%0,%1,%2,%3}, {%4,%5,%6,%7}, {%8,%9}, {%0,%1,%2,%3};"
        : "+f"(c[0]), "+f"(c[1]), "+f"(c[2]), "+f"(c[3])
        : "r"(a[0]), "r"(a[1]), "r"(a[2]), "r"(a[3]), "r"(bf[0]), "r"(bf[1]));
}
// packed f32x2 (Blackwell)
__device__ __forceinline__ u64 pk2(float lo, float hi) {
    u64 r; asm("mov.b64 %0, {%1, %2};" : "=l"(r) : "f"(lo), "f"(hi)); return r;
}
__device__ __forceinline__ void upk2(float& lo, float& hi, u64 v) {
    asm("mov.b64 {%0, %1}, %2;" : "=f"(lo), "=f"(hi) : "l"(v));
}
__device__ __forceinline__ u64 fma2(u64 a, u64 b, u64 c) {
    u64 d; asm("fma.rn.f32x2 %0, %1, %2, %3;" : "=l"(d) : "l"(a), "l"(b), "l"(c)); return d;
}
__device__ __forceinline__ u64 mul2(u64 a, u64 b) {
    u64 d; asm("mul.rn.f32x2 %0, %1, %2;" : "=l"(d) : "l"(a), "l"(b)); return d;
}
__device__ __forceinline__ u64 add2(u64 a, u64 b) {
    u64 d; asm("add.rn.f32x2 %0, %1, %2;" : "=l"(d) : "l"(a), "l"(b)); return d;
}

// ---------------------------------------------------------------------------
// Pass 1: per-slab stats + bf16 conversion + per-point norms + fused finalize.
// grid (32 slabs of 128 points, 4 batches), 256 threads.
// ---------------------------------------------------------------------------
__global__ void stats_kernel(const float* __restrict__ x, const float* __restrict__ y) {
    const int s = blockIdx.x, b = blockIdx.y, t = threadIdx.x;
    const int w = t >> 5, lane = t & 31;
    const int d = t & 63, g = t >> 6;
    const int pbase = s * 128 + g * 32;   // 32 points per group, single region
    const float* base = (pbase < NPTS)
        ? x + ((size_t)b * NPTS + pbase) * D
        : y + ((size_t)b * NPTS + (pbase - NPTS)) * D;

    float vsum = 0.f, ssum = 0.f;
    #pragma unroll 8
    for (int r = 0; r < 32; ++r) {
        float v = base[(size_t)r * D + d];
        vsum += v;
        ssum = fmaf(v, v, ssum);
    }
    __shared__ float sv[4][64];
    sv[g][d] = vsum;

    // ssum: shuffle reduce within warp, cross-warp via 8-slot smem
    #pragma unroll
    for (int o = 16; o > 0; o >>= 1) ssum += __shfl_down_sync(0xffffffffu, ssum, o);
    __shared__ float swr[8];
    if (lane == 0) swr[w] = ssum;
    __syncthreads();
    if (t < 64) g_vec[b][s][t] = sv[0][t] + sv[1][t] + sv[2][t] + sv[3][t];
    if (t == 0) {
        float tot = 0.f;
        #pragma unroll
        for (int ww = 0; ww < 8; ++ww) tot += swr[ww];
        g_s1[b][s] = tot;
    }

    // bf16 conversion + squared norm: 2 threads per point (half-row each)
    {
        const int p0 = s * 128 + (t >> 1);
        const int half = t & 1;
        const float* row = ((p0 < NPTS)
            ? x + ((size_t)b * NPTS + p0) * D
            : y + ((size_t)b * NPTS + (p0 - NPTS)) * D) + half * 32;
        uint2* dst = (uint2*)&g_bf[b][p0][half * 32];
        float acc = 0.f;
        #pragma unroll
        for (int k = 0; k < 8; ++k) {
            float4 v = *(const float4*)(row + k * 4);
            float a0 = __bfloat162float(__float2bfloat16(v.x));
            float a1 = __bfloat162float(__float2bfloat16(v.y));
            float a2 = __bfloat162float(__float2bfloat16(v.z));
            float a3 = __bfloat162float(__float2bfloat16(v.w));
            acc = fmaf(a0, a0, acc);
            acc = fmaf(a1, a1, acc);
            acc = fmaf(a2, a2, acc);
            acc = fmaf(a3, a3, acc);
            uint2 pk;
            pk.x = pack_bf16x2(v.x, v.y);
            pk.y = pack_bf16x2(v.z, v.w);
            dst[k] = pk;
        }
        float other = __shfl_xor_sync(0xffffffffu, acc, 1);
        if (half == 0) g_sqn[b][p0] = acc + other;
    }

    __shared__ int islast;
    __syncthreads();
    if (t == 0) {
        __threadfence();
        int old = atomicAdd(&g_cnt1, 1);
        islast = (old == SLABS * NB - 1);
    }
    __syncthreads();

    if (islast) {
        const int bb = t >> 6;
        float v = 0.f;
        #pragma unroll
        for (int ss2 = 0; ss2 < SLABS; ++ss2) v += g_vec[bb][ss2][d];
        float vv = v * v;
        #pragma unroll
        for (int o = 16; o > 0; o >>= 1) vv += __shfl_down_sync(0xffffffffu, vv, o);
        __shared__ float red[8];
        if (lane == 0) red[w] = vv;
        __syncthreads();
        if (t < NB) {
            float VV = red[2 * t] + red[2 * t + 1];
            float S1 = 0.f;
            #pragma unroll
            for (int ss2 = 0; ss2 < SLABS; ++ss2) S1 += g_s1[t][ss2];
            float sumL2 = 2.f * (float)NTOT * S1 - 2.f * VV;
            float bwb = sumL2 / 16773120.f;   // N^2 - N
            g_negc[t] = -1.f / (4.f * bwb);
        }
        if (t == 0) g_cnt1 = 0;   // reset for graph replay
    }
}

// ---------------------------------------------------------------------------
// Pass 2: bf16 mma (ldmatrix) Gram + packed-f32x2 Gaussian epilogue,
// triangular tiles, fused final reduction.
// grid (528, 4), 256 threads (8 warps, warp tile 64x32 as two 32x32 M-halves).
// ---------------------------------------------------------------------------
__global__ void __launch_bounds__(256, 3)
mmd_tile_kernel(float* __restrict__ out) {
    extern __shared__ float sm[];
    uint32_t* As = (uint32_t*)sm;                     // [128][SW] bf16x2 words
    uint32_t* Bs = As + BM * SW;
    float* sqA = (float*)(Bs + BM * SW);              // [128] pre-scaled by negc2
    float* sqB = sqA + BM;

    const int t = threadIdx.x;
    const int w = t >> 5, lane = t & 31;
    const int gid = lane >> 2, tig = lane & 3;
    const int b = blockIdx.y;

    // triangular decode: tri -> (by, bx), bx <= by
    const int tri = blockIdx.x;
    int by = (int)((sqrtf(8.f * (float)tri + 1.f) - 1.f) * 0.5f);
    while ((by + 1) * (by + 2) / 2 <= tri) ++by;
    while (by * (by + 1) / 2 > tri) --by;
    const int bx = tri - by * (by + 1) / 2;

    const float negc2 = g_negc[b] * LOG2E;
    const float m2 = -2.f * negc2;
    const u64 M2 = pk2(m2, m2);

    // Pre-scaled squared norms
    if (t < 128) sqA[t] = g_sqn[b][by * BM + t] * negc2;
    else         sqB[t - 128] = g_sqn[b][bx * BM + (t - 128)] * negc2;

    // Copy bf16 tiles (128 rows x 32 words) into smem, row stride SW words.
    {
        const uint4* srcA = (const uint4*)&g_bf[b][by * BM][0];   // 1024 uint4
        const uint4* srcB = (const uint4*)&g_bf[b][bx * BM][0];
        #pragma unroll
        for (int i = 0; i < 4; ++i) {
            int idx = t + i * 256;
            int row = idx >> 3, q = idx & 7;
            *(uint4*)&As[row * SW + q * 4] = srcA[idx];
            *(uint4*)&Bs[row * SW + q * 4] = srcB[idx];
        }
    }
    __syncthreads();

    // Warp tile: rows [m0, m0+64) as two 32-row halves, cols [n0, n0+32)
    const int m0 = (w & 1) * 64;
    const int n0 = (w >> 1) * 32;
    const uint32_t smb = smem_u32(sm);

    uint32_t a_addr[2][2];   // [half][mf]
    #pragma unroll
    for (int half = 0; half < 2; ++half)
        #pragma unroll
        for (int mf = 0; mf < 2; ++mf) {
            int row = m0 + half * 32 + mf * 16 + (lane & 15);
            a_addr[half][mf] = smb + (uint32_t)(row * SW + (lane >> 4) * 4) * 4u;
        }
    uint32_t b_addr[2];      // [j] 16-col groups
    #pragma unroll
    for (int j = 0; j < 2; ++j) {
        const int bcol = n0 + j * 16 + ((lane >> 4) << 3) + (lane & 7);
        b_addr[j] = smb + (uint32_t)(BM * SW + bcol * SW + ((lane >> 3) & 1) * 4) * 4u;
    }

    // Hoisted packed sqB for the 4 column frags (same cols in both halves)
    u64 SB[4];
    #pragma unroll
    for (int nf = 0; nf < 4; ++nf) {
        const int c0i = n0 + nf * 8 + tig * 2;
        SB[nf] = pk2(sqB[c0i], sqB[c0i + 1]);
    }

    u64 acc2 = pk2(0.f, 0.f);
    #pragma unroll
    for (int half = 0; half < 2; ++half) {
        float c[2][4][4];
        #pragma unroll
        for (int mf = 0; mf < 2; ++mf)
            #pragma unroll
            for (int nf = 0; nf < 4; ++nf)
                #pragma unroll
                for (int q = 0; q < 4; ++q) c[mf][nf][q] = 0.f;

        #pragma unroll
        for (int ks = 0; ks < 4; ++ks) {
            uint32_t a[2][4], bf[2][4];
            ldsm_x4(a[0], a_addr[half][0] + ks * 32);
            ldsm_x4(a[1], a_addr[half][1] + ks * 32);
            ldsm_x4(bf[0], b_addr[0] + ks * 32);
            ldsm_x4(bf[1], b_addr[1] + ks * 32);
            #pragma unroll
            for (int mf = 0; mf < 2; ++mf) {
                mma_bf16(c[mf][0], a[mf], &bf[0][0]);
                mma_bf16(c[mf][1], a[mf], &bf[0][2]);
                mma_bf16(c[mf][2], a[mf], &bf[1][0]);
                mma_bf16(c[mf][3], a[mf], &bf[1][2]);
            }
        }

        // Packed epilogue for this half
        #pragma unroll
        for (int mf = 0; mf < 2; ++mf) {
            const int r0i = m0 + half * 32 + mf * 16 + gid;
            const float sA0 = sqA[r0i], sA1 = sqA[r0i + 8];
            const u64 SA0 = pk2(sA0, sA0);
            const u64 SA1 = pk2(sA1, sA1);
            #pragma unroll
            for (int nf = 0; nf < 4; ++nf) {
                const u64 S0 = add2(SA0, SB[nf]);
                const u64 S1 = add2(SA1, SB[nf]);
                const float* cf = c[mf][nf];
                #pragma unroll
                for (int pr = 0; pr < 2; ++pr) {            // row gid / gid+8
                    u64 C = pk2(cf[pr * 2], cf[pr * 2 + 1]);
                    u64 L = fma2(M2, C, pr ? S1 : S0);      // negc2 * L2 (log2 units)
                    float l0, l1;
                    upk2(l0, l1, L);
                    u64 E = pk2(ex2f(l0), ex2f(l1));
                    u64 E2 = mul2(E, E);
                    u64 E4 = mul2(E2, E2);
                    u64 E8 = mul2(E4, E4);
                    u64 T = fma2(E8, E8, E8);               // e16 + e8
                    acc2 = add2(acc2, add2(add2(E, E2), add2(E4, T)));
                }
            }
        }
    }

    float llo, lhi;
    upk2(llo, lhi, acc2);
    float local = llo + lhi;

    // Block reduce + signed/weighted write + fused final reduction
    #pragma unroll
    for (int o = 16; o > 0; o >>= 1) local += __shfl_down_sync(0xffffffffu, local, o);
    __shared__ float red[8];
    if (lane == 0) red[w] = local;
    __syncthreads();

    __shared__ int islast;
    if (t == 0) {
        float tot = 0.f;
        #pragma unroll
        for (int ww = 0; ww < 8; ++ww) tot += red[ww];
        float sgn = ((by < 16) == (bx < 16)) ? 1.f : -1.f;
        float wt = (bx == by) ? 1.f : 2.f;
        g_part[b][tri] = tot * sgn * wt;
        __threadfence();
        int old = atomicAdd(&g_cnt2[b], 1);
        islast = (old == NTRI - 1);
    }
    __syncthreads();

    if (islast) {
        float s = 0.f;
        for (int idx = t; idx < NTRI; idx += 256) s += g_part[b][idx];
        #pragma unroll
        for (int o = 16; o > 0; o >>= 1) s += __shfl_down_sync(0xffffffffu, s, o);
        __shared__ float red2[8];
        if (lane == 0) red2[w] = s;
        __syncthreads();
        if (t == 0) {
            float tot = 0.f;
            #pragma unroll
            for (int ww = 0; ww < 8; ++ww) tot += red2[ww];
            out[b] = tot * (1.f / ((float)NPTS * (float)NPTS));
            g_cnt2[b] = 0;   // reset for graph replay
        }
    }
}

extern "C" void kernel_launch(void* const* d_in, const int* in_sizes, int n_in,
                              void* d_out, int out_size) {
    const float* x = (const float*)d_in[0];
    const float* y = (const float*)d_in[1];
    float* out = (float*)d_out;

    const int smem_bytes = (2 * BM * SW + 2 * BM) * (int)sizeof(float);  // 37888
    cudaFuncSetAttribute(mmd_tile_kernel,
                         cudaFuncAttributeMaxDynamicSharedMemorySize, smem_bytes);

    stats_kernel<<<dim3(SLABS, NB), 256>>>(x, y);
    mmd_tile_kernel<<<dim3(NTRI, NB), 256, smem_bytes>>>(out);
}